// round 15
// baseline (speedup 1.0000x reference)
#include <cuda_runtime.h>
#include <cuda_fp16.h>
#include <math.h>

#define Bn 4
#define Qn 8192
#define Dm 256
#define Lv 2
#define Pp 8
#define H0 128
#define W0 128
#define H1 64
#define W1 64
#define EPSV 1e-5f
#define NQ (Bn * Qn)          // 32768 total queries
#define MAP1_BASE (Bn * H0 * W0 * Dm)   // element offset of level-1 maps

// Scratch (device globals — no allocations allowed)
__device__ __half g_maps[Bn * (H0 * W0 + H1 * W1) * Dm];  // both maps, HWC fp16
__device__ __half g_pre16[NQ * Dm];            // pre-Wout accumulator (fp16)
__device__ __half g_Wout16[Dm * Dm];           // Wout in fp16
__device__ __half g_Wcat16h[256 * 64];         // packed proj weights hi, k-major [k][j]
__device__ __half g_Wcat16l[256 * 64];         // packed proj weights lo (residual)
__device__ float  g_bcatP[64];
__device__ float  g_dots[NQ * 64];             // projection outputs per query

__device__ __forceinline__ unsigned smem_u32(const void* p) {
    return (unsigned)__cvta_generic_to_shared(p);
}
__device__ __forceinline__ void cpa16(unsigned d, const void* s) {
    asm volatile("cp.async.cg.shared.global [%0], [%1], 16;" :: "r"(d), "l"(s));
}

// ---------------------------------------------------------------------------
// Kernel 0 (merged prep): blocks 0..63 pack proj weights; 64..191 pack Wout;
// blocks 192.. : map transposes (fp32 NCHW -> fp16 NHWC), flattened 3D decode.
// ---------------------------------------------------------------------------
#define TR_BLOCKS_X 640                 // 512 (map0) + 128 (map1) hw-tiles
#define PREP_BLOCKS (192 + TR_BLOCKS_X * (Dm / 64) * Bn)

__global__ __launch_bounds__(256) void prep_kernel(
    const float* __restrict__ Wrd,  const float* __restrict__ brd,
    const float* __restrict__ Woff, const float* __restrict__ boff,
    const float* __restrict__ Wattn,const float* __restrict__ battn,
    const float* __restrict__ Wout,
    const float* __restrict__ map0, const float* __restrict__ map1)
{
    __shared__ float tile[64][33];
    const int bxg = blockIdx.x;
    const int t   = threadIdx.x;

    if (bxg < 64) {
        int j = bxg, k = t;
        float v = 0.f, bv = 0.f;
        if (j < 4)       { v = Wrd  [k * 4  + j];      bv = brd  [j]; }
        else if (j < 36) { v = Woff [k * 32 + (j-4)];  bv = boff [j-4]; }
        else if (j < 52) { v = Wattn[k * 16 + (j-36)]; bv = battn[j-36]; }
        __half hi = __float2half_rn(v);
        __half lo = __float2half_rn(v - __half2float(hi));
        g_Wcat16h[k * 64 + j] = hi;
        g_Wcat16l[k * 64 + j] = lo;
        if (k == 0) g_bcatP[j] = bv;
        return;
    }
    if (bxg < 192) {
        int idx = (bxg - 64) * 256 + t;    // half2 index
        float2 v = ((const float2*)Wout)[idx];
        ((__half2*)g_Wout16)[idx] = __floats2half2_rn(v.x, v.y);
        return;
    }

    // ---- transpose part: decode flattened (bx, dy, b) ----
    const int fb = bxg - 192;
    const int bx = fb % TR_BLOCKS_X;
    const int dy = (fb / TR_BLOCKS_X) % (Dm / 64);
    const int b  = fb / (TR_BLOCKS_X * (Dm / 64));

    const int level = (bx >= 512);
    const int HW    = level ? (H1 * W1) : (H0 * W0);
    const int hw0   = (level ? (bx - 512) : bx) * 32;
    const float* in = level ? map1 : map0;
    __half* out     = g_maps + (level ? MAP1_BASE : 0);

    const int d0  = dy * 64;
    const int tx  = t & 31;
    const int ty  = t >> 5;

    const float* inb = in + (size_t)b * Dm * HW;
    __half* outb = out + (size_t)b * HW * Dm;

#pragma unroll
    for (int i = 0; i < 8; i++) {
        int d = d0 + ty + 8 * i;
        tile[ty + 8 * i][tx] = inb[(size_t)d * HW + hw0 + tx];
    }
    __syncthreads();

#pragma unroll
    for (int i = 0; i < 4; i++) {
        int hw = ty + 8 * i;
        __half2 v = __floats2half2_rn(tile[2 * tx][hw], tile[2 * tx + 1][hw]);
        ((__half2*)(outb + (size_t)(hw0 + hw) * Dm + d0))[tx] = v;
    }
}

// ---------------------------------------------------------------------------
// Kernel 2: projection GEMM via split-fp16 HMMA (fp32-accurate), 2-stage
// pipeline. BM=64 (grid 512), BK=32 (8 iters), 8 warps = 4(m) x 2(n).
// ---------------------------------------------------------------------------
#define PAP 40        // A pitch in halves
#define PBP 72        // B pitch in halves

__global__ __launch_bounds__(256) void proj_hmma_kernel(const float* __restrict__ q)
{
    __shared__ __align__(16) __half Ah[2][64 * PAP];
    __shared__ __align__(16) __half Al[2][64 * PAP];
    __shared__ __align__(16) __half Bh[2][32 * PBP];
    __shared__ __align__(16) __half Bl[2][32 * PBP];

    const int tid  = threadIdx.x;
    const int wid  = tid >> 5;
    const int lane = tid & 31;
    const int m0 = blockIdx.x * 64;
    const int wm = (wid & 3) * 16;       // warp m offset
    const int wn = (wid >> 2) * 32;      // warp n offset

    const int lr = lane & 15;
    const int lc = (lane >> 4) * 8;

    const int ar = tid >> 3;             // 0..31 (+32 for second)
    const int ac = (tid & 7) * 4;
    const int br = tid >> 3;
    const int bc = (tid & 7) * 8;

    float4 ra0, ra1;
    float acc[4][4] = {};                // [nt][frag]

    // ---- prologue: tile 0 ----
    ra0 = *(const float4*)&q[(size_t)(m0 + ar) * 256 + ac];
    ra1 = *(const float4*)&q[(size_t)(m0 + ar + 32) * 256 + ac];
    cpa16(smem_u32(&Bh[0][br * PBP + bc]), &g_Wcat16h[br * 64 + bc]);
    cpa16(smem_u32(&Bl[0][br * PBP + bc]), &g_Wcat16l[br * 64 + bc]);
    asm volatile("cp.async.commit_group;");
    {
        float f0[4] = {ra0.x, ra0.y, ra0.z, ra0.w};
        float f1[4] = {ra1.x, ra1.y, ra1.z, ra1.w};
        __half h0[4], l0[4], h1[4], l1[4];
#pragma unroll
        for (int j = 0; j < 4; j++) {
            h0[j] = __float2half_rn(f0[j]);
            l0[j] = __float2half_rn(f0[j] - __half2float(h0[j]));
            h1[j] = __float2half_rn(f1[j]);
            l1[j] = __float2half_rn(f1[j] - __half2float(h1[j]));
        }
        int o0 = ar * PAP + ac;
        int o1 = (ar + 32) * PAP + ac;
        *(__half2*)&Ah[0][o0]     = __halves2half2(h0[0], h0[1]);
        *(__half2*)&Ah[0][o0 + 2] = __halves2half2(h0[2], h0[3]);
        *(__half2*)&Al[0][o0]     = __halves2half2(l0[0], l0[1]);
        *(__half2*)&Al[0][o0 + 2] = __halves2half2(l0[2], l0[3]);
        *(__half2*)&Ah[0][o1]     = __halves2half2(h1[0], h1[1]);
        *(__half2*)&Ah[0][o1 + 2] = __halves2half2(h1[2], h1[3]);
        *(__half2*)&Al[0][o1]     = __halves2half2(l1[0], l1[1]);
        *(__half2*)&Al[0][o1 + 2] = __halves2half2(l1[2], l1[3]);
    }
    asm volatile("cp.async.wait_group 0;");
    __syncthreads();

#pragma unroll 1
    for (int it = 0; it < 8; it++) {
        const int s = it & 1;

        if (it < 7) {
            const int k0n = (it + 1) * 32;
            ra0 = *(const float4*)&q[(size_t)(m0 + ar) * 256 + k0n + ac];
            ra1 = *(const float4*)&q[(size_t)(m0 + ar + 32) * 256 + k0n + ac];
            cpa16(smem_u32(&Bh[s ^ 1][br * PBP + bc]), &g_Wcat16h[(k0n + br) * 64 + bc]);
            cpa16(smem_u32(&Bl[s ^ 1][br * PBP + bc]), &g_Wcat16l[(k0n + br) * 64 + bc]);
            asm volatile("cp.async.commit_group;");
        }

#pragma unroll
        for (int kc = 0; kc < 2; kc++) {
            const int kk = kc * 16;
            unsigned a_h[4], a_l[4];
            {
                unsigned addr = smem_u32(&Ah[s][(wm + lr) * PAP + kk + lc]);
                asm volatile(
                    "ldmatrix.sync.aligned.m8n8.x4.shared.b16 {%0,%1,%2,%3}, [%4];"
                    : "=r"(a_h[0]), "=r"(a_h[1]), "=r"(a_h[2]), "=r"(a_h[3]) : "r"(addr));
                addr = smem_u32(&Al[s][(wm + lr) * PAP + kk + lc]);
                asm volatile(
                    "ldmatrix.sync.aligned.m8n8.x4.shared.b16 {%0,%1,%2,%3}, [%4];"
                    : "=r"(a_l[0]), "=r"(a_l[1]), "=r"(a_l[2]), "=r"(a_l[3]) : "r"(addr));
            }
            unsigned b_h[2][4], b_l[2][4];
#pragma unroll
            for (int ng = 0; ng < 2; ng++) {
                unsigned addr = smem_u32(&Bh[s][(kk + lr) * PBP + wn + ng * 16 + lc]);
                asm volatile(
                    "ldmatrix.sync.aligned.m8n8.x4.trans.shared.b16 {%0,%1,%2,%3}, [%4];"
                    : "=r"(b_h[ng][0]), "=r"(b_h[ng][1]), "=r"(b_h[ng][2]), "=r"(b_h[ng][3])
                    : "r"(addr));
                addr = smem_u32(&Bl[s][(kk + lr) * PBP + wn + ng * 16 + lc]);
                asm volatile(
                    "ldmatrix.sync.aligned.m8n8.x4.trans.shared.b16 {%0,%1,%2,%3}, [%4];"
                    : "=r"(b_l[ng][0]), "=r"(b_l[ng][1]), "=r"(b_l[ng][2]), "=r"(b_l[ng][3])
                    : "r"(addr));
            }
#pragma unroll
            for (int nt = 0; nt < 4; nt++) {
                unsigned bh0 = b_h[nt >> 1][(nt & 1) * 2 + 0];
                unsigned bh1 = b_h[nt >> 1][(nt & 1) * 2 + 1];
                unsigned bl0 = b_l[nt >> 1][(nt & 1) * 2 + 0];
                unsigned bl1 = b_l[nt >> 1][(nt & 1) * 2 + 1];
                asm volatile(
                    "mma.sync.aligned.m16n8k16.row.col.f32.f16.f16.f32 "
                    "{%0,%1,%2,%3}, {%4,%5,%6,%7}, {%8,%9}, {%0,%1,%2,%3};"
                    : "+f"(acc[nt][0]), "+f"(acc[nt][1]), "+f"(acc[nt][2]), "+f"(acc[nt][3])
                    : "r"(a_h[0]), "r"(a_h[1]), "r"(a_h[2]), "r"(a_h[3]), "r"(bh0), "r"(bh1));
                asm volatile(
                    "mma.sync.aligned.m16n8k16.row.col.f32.f16.f16.f32 "
                    "{%0,%1,%2,%3}, {%4,%5,%6,%7}, {%8,%9}, {%0,%1,%2,%3};"
                    : "+f"(acc[nt][0]), "+f"(acc[nt][1]), "+f"(acc[nt][2]), "+f"(acc[nt][3])
                    : "r"(a_h[0]), "r"(a_h[1]), "r"(a_h[2]), "r"(a_h[3]), "r"(bl0), "r"(bl1));
                asm volatile(
                    "mma.sync.aligned.m16n8k16.row.col.f32.f16.f16.f32 "
                    "{%0,%1,%2,%3}, {%4,%5,%6,%7}, {%8,%9}, {%0,%1,%2,%3};"
                    : "+f"(acc[nt][0]), "+f"(acc[nt][1]), "+f"(acc[nt][2]), "+f"(acc[nt][3])
                    : "r"(a_l[0]), "r"(a_l[1]), "r"(a_l[2]), "r"(a_l[3]), "r"(bh0), "r"(bh1));
            }
        }

        if (it < 7) {
            const int sn = s ^ 1;
            float f0[4] = {ra0.x, ra0.y, ra0.z, ra0.w};
            float f1[4] = {ra1.x, ra1.y, ra1.z, ra1.w};
            __half h0[4], l0[4], h1[4], l1[4];
#pragma unroll
            for (int j = 0; j < 4; j++) {
                h0[j] = __float2half_rn(f0[j]);
                l0[j] = __float2half_rn(f0[j] - __half2float(h0[j]));
                h1[j] = __float2half_rn(f1[j]);
                l1[j] = __float2half_rn(f1[j] - __half2float(h1[j]));
            }
            int o0 = ar * PAP + ac;
            int o1 = (ar + 32) * PAP + ac;
            *(__half2*)&Ah[sn][o0]     = __halves2half2(h0[0], h0[1]);
            *(__half2*)&Ah[sn][o0 + 2] = __halves2half2(h0[2], h0[3]);
            *(__half2*)&Al[sn][o0]     = __halves2half2(l0[0], l0[1]);
            *(__half2*)&Al[sn][o0 + 2] = __halves2half2(l0[2], l0[3]);
            *(__half2*)&Ah[sn][o1]     = __halves2half2(h1[0], h1[1]);
            *(__half2*)&Ah[sn][o1 + 2] = __halves2half2(h1[2], h1[3]);
            *(__half2*)&Al[sn][o1]     = __halves2half2(l1[0], l1[1]);
            *(__half2*)&Al[sn][o1 + 2] = __halves2half2(l1[2], l1[3]);
            asm volatile("cp.async.wait_group 0;");
        }
        __syncthreads();
    }

    // epilogue: + bias -> g_dots (fp32)
    const int gr = lane >> 2;
    const int gc = (lane & 3) * 2;
#pragma unroll
    for (int nt = 0; nt < 4; nt++) {
        int col = wn + nt * 8 + gc;
        float2 bv = *(const float2*)&g_bcatP[col];
        int row0 = m0 + wm + gr;
        float2 o0 = make_float2(acc[nt][0] + bv.x, acc[nt][1] + bv.y);
        float2 o1 = make_float2(acc[nt][2] + bv.x, acc[nt][3] + bv.y);
        *(float2*)&g_dots[(size_t)row0 * 64 + col]       = o0;
        *(float2*)&g_dots[(size_t)(row0 + 8) * 64 + col] = o1;
    }
}

// ---------------------------------------------------------------------------
// Kernel 3: FUSED coords + softmax + gather. 16 queries per block.
// __launch_bounds__(256, 6) caps regs to lift occupancy (5 -> 6 blocks/SM).
// ---------------------------------------------------------------------------
__global__ __launch_bounds__(256, 6) void gather_fused_kernel(
    const float* __restrict__ base_ref)
{
    __shared__ int4  soff[16][16];     // byte offsets of 4 corners
    __shared__ uint4 scw [16][16];     // 4x half2 corner weights (attn folded)

    const int tid = threadIdx.x;
    const int q0  = blockIdx.x * 16;

    // ---------- Phase 1: coordinates + softmax ----------
    {
        const int qq = tid >> 4;          // query within block (0..15)
        const int p  = tid & 15;          // point (0..15)
        const int qidx = q0 + qq;
        const int b = qidx >> 13;         // Qn = 8192

        const float* dots = &g_dots[(size_t)qidx * 64];

        float logit = dots[36 + p];
        float m = logit;
#pragma unroll
        for (int o = 8; o; o >>= 1)
            m = fmaxf(m, __shfl_xor_sync(0xffffffffu, m, o));
        float e = expf(logit - m);
        float esum = e;
#pragma unroll
        for (int o = 8; o; o >>= 1)
            esum += __shfl_xor_sync(0xffffffffu, esum, o);
        float wattn = e / esum;

        const int l  = p >> 3;
        const int pp = p & 7;
        const int Wl = l ? W1 : W0;
        const int Hl = l ? H1 : H0;

        float bx = base_ref[(b * Lv + l) * 2 + 0];
        float by = base_ref[(b * Lv + l) * 2 + 1];
        bx = fminf(fmaxf(bx, EPSV), 1.f - EPSV);
        by = fminf(fmaxf(by, EPSV), 1.f - EPSV);
        float lbx = logf(bx / (1.f - bx));
        float lby = logf(by / (1.f - by));
        float rx = 1.f / (1.f + expf(-(lbx + dots[l * 2 + 0])));
        float ry = 1.f / (1.f + expf(-(lby + dots[l * 2 + 1])));

        float ox = dots[4 + l * 16 + pp * 2 + 0];
        float oy = dots[4 + l * 16 + pp * 2 + 1];
        float lx = rx + ox / (float)Wl;
        float ly = ry + oy / (float)Hl;
        if (l == 1) ly = ly - floorf(ly);   // jnp.remainder(ly, 1.0)

        float x = lx * (float)Wl - 0.5f;
        float y = ly * (float)Hl - 0.5f;
        x = fminf(fmaxf(x, 0.f), (float)(Wl - 1));
        y = fminf(fmaxf(y, 0.f), (float)(Hl - 1));
        float x0f = floorf(x), y0f = floorf(y);
        float wx = x - x0f, wy = y - y0f;
        int x0 = (int)x0f, y0 = (int)y0f;
        int x1 = min(x0 + 1, Wl - 1);
        int y1 = min(y0 + 1, Hl - 1);
        int base = (l ? MAP1_BASE : 0) + b * Hl * Wl * Dm;

        int4 off;   // byte offsets (element * 2)
        off.x = (base + (y0 * Wl + x0) * Dm) * 2;
        off.y = (base + (y0 * Wl + x1) * Dm) * 2;
        off.z = (base + (y1 * Wl + x0) * Dm) * 2;
        off.w = (base + (y1 * Wl + x1) * Dm) * 2;
        soff[qq][p] = off;

        __half2 c00 = __float2half2_rn((1.f - wx) * (1.f - wy) * wattn);
        __half2 c01 = __float2half2_rn(wx * (1.f - wy) * wattn);
        __half2 c10 = __float2half2_rn((1.f - wx) * wy * wattn);
        __half2 c11 = __float2half2_rn(wx * wy * wattn);
        uint4 pk;
        pk.x = *(unsigned*)&c00;
        pk.y = *(unsigned*)&c01;
        pk.z = *(unsigned*)&c10;
        pk.w = *(unsigned*)&c11;
        scw[qq][p] = pk;
    }
    __syncthreads();

    // ---------- Phase 2: gather ----------
    const int w    = tid >> 5;
    const int lane = tid & 31;
    const char* basep = (const char*)g_maps + lane * 16;

#pragma unroll
    for (int h = 0; h < 2; h++) {
        const int qq = 2 * w + h;
        float acc[8] = {};

#pragma unroll
        for (int p = 0; p < 16; p++) {
            const int4  o  = soff[qq][p];
            const uint4 pk = scw[qq][p];
            __half2 c00 = *(__half2*)&pk.x;
            __half2 c01 = *(__half2*)&pk.y;
            __half2 c10 = *(__half2*)&pk.z;
            __half2 c11 = *(__half2*)&pk.w;

            uint4 r00 = __ldg((const uint4*)(basep + o.x));
            uint4 r01 = __ldg((const uint4*)(basep + o.y));
            uint4 r10 = __ldg((const uint4*)(basep + o.z));
            uint4 r11 = __ldg((const uint4*)(basep + o.w));
            const __half2* h00 = (const __half2*)&r00;
            const __half2* h01 = (const __half2*)&r01;
            const __half2* h10 = (const __half2*)&r10;
            const __half2* h11 = (const __half2*)&r11;

#pragma unroll
            for (int j = 0; j < 4; j++) {
                __half2 t = __hmul2(c00, h00[j]);
                t = __hfma2(c01, h01[j], t);
                t = __hfma2(c10, h10[j], t);
                t = __hfma2(c11, h11[j], t);
                float2 f = __half22float2(t);
                acc[2 * j + 0] += f.x;
                acc[2 * j + 1] += f.y;
            }
        }

        __half2 hv[4];
#pragma unroll
        for (int j = 0; j < 4; j++)
            hv[j] = __floats2half2_rn(acc[2 * j], acc[2 * j + 1]);
        *(uint4*)&g_pre16[(size_t)(q0 + qq) * 256 + lane * 8] = *(uint4*)hv;
    }
}

// ---------------------------------------------------------------------------
// Kernel 4: C = g_pre16(M,256) @ Wout16(256,256) + bout  via HMMA m16n8k16.
// ---------------------------------------------------------------------------
#define HAPITCH 40
#define HBPITCH 136

__global__ __launch_bounds__(256) void gemm_hmma_kernel(
    const float* __restrict__ bias, float* __restrict__ C)
{
    __shared__ __align__(16) __half As[2][128 * HAPITCH];
    __shared__ __align__(16) __half Bs[2][32 * HBPITCH];

    const int tid  = threadIdx.x;
    const int wid  = tid >> 5;
    const int lane = tid & 31;
    const int m0 = blockIdx.y * 128;
    const int n0 = blockIdx.x * 128;
    const int wm = (wid & 1) * 64;
    const int wn = (wid >> 1) * 32;

    const int ara = tid >> 2;
    const int aca = (tid & 3) * 8;
    const int brb = tid >> 4;
    const int bcb = (tid & 15) * 8;

    float acc[4][4][4] = {};

    const int lr = lane & 15;
    const int lc = (lane >> 4) * 8;

    {
        const int k0 = 0;
        cpa16(smem_u32(&As[0][ara * HAPITCH + aca]),
              &g_pre16[(size_t)(m0 + ara) * 256 + k0 + aca]);
        cpa16(smem_u32(&As[0][(ara + 64) * HAPITCH + aca]),
              &g_pre16[(size_t)(m0 + ara + 64) * 256 + k0 + aca]);
        cpa16(smem_u32(&Bs[0][brb * HBPITCH + bcb]),
              &g_Wout16[(size_t)(k0 + brb) * 256 + n0 + bcb]);
        cpa16(smem_u32(&Bs[0][(brb + 16) * HBPITCH + bcb]),
              &g_Wout16[(size_t)(k0 + brb + 16) * 256 + n0 + bcb]);
        asm volatile("cp.async.commit_group;");
    }

#pragma unroll
    for (int it = 0; it < 8; it++) {
        if (it + 1 < 8) {
            const int k0 = (it + 1) * 32;
            const int s = (it + 1) & 1;
            cpa16(smem_u32(&As[s][ara * HAPITCH + aca]),
                  &g_pre16[(size_t)(m0 + ara) * 256 + k0 + aca]);
            cpa16(smem_u32(&As[s][(ara + 64) * HAPITCH + aca]),
                  &g_pre16[(size_t)(m0 + ara + 64) * 256 + k0 + aca]);
            cpa16(smem_u32(&Bs[s][brb * HBPITCH + bcb]),
                  &g_Wout16[(size_t)(k0 + brb) * 256 + n0 + bcb]);
            cpa16(smem_u32(&Bs[s][(brb + 16) * HBPITCH + bcb]),
                  &g_Wout16[(size_t)(k0 + brb + 16) * 256 + n0 + bcb]);
            asm volatile("cp.async.commit_group;");
            asm volatile("cp.async.wait_group 1;");
        } else {
            asm volatile("cp.async.wait_group 0;");
        }
        __syncthreads();

        const int s = it & 1;
#pragma unroll
        for (int kk = 0; kk < 32; kk += 16) {
            unsigned a[4][4];
#pragma unroll
            for (int mt = 0; mt < 4; mt++) {
                unsigned addr = smem_u32(&As[s][(wm + mt * 16 + lr) * HAPITCH + kk + lc]);
                asm volatile(
                    "ldmatrix.sync.aligned.m8n8.x4.shared.b16 {%0,%1,%2,%3}, [%4];"
                    : "=r"(a[mt][0]), "=r"(a[mt][1]), "=r"(a[mt][2]), "=r"(a[mt][3])
                    : "r"(addr));
            }
            unsigned b[2][4];
#pragma unroll
            for (int ng = 0; ng < 2; ng++) {
                unsigned addr = smem_u32(&Bs[s][(kk + lr) * HBPITCH + wn + ng * 16 + lc]);
                asm volatile(
                    "ldmatrix.sync.aligned.m8n8.x4.trans.shared.b16 {%0,%1,%2,%3}, [%4];"
                    : "=r"(b[ng][0]), "=r"(b[ng][1]), "=r"(b[ng][2]), "=r"(b[ng][3])
                    : "r"(addr));
            }
#pragma unroll
            for (int mt = 0; mt < 4; mt++) {
#pragma unroll
                for (int nt = 0; nt < 4; nt++) {
                    unsigned b0 = b[nt >> 1][(nt & 1) * 2 + 0];
                    unsigned b1 = b[nt >> 1][(nt & 1) * 2 + 1];
                    asm volatile(
                        "mma.sync.aligned.m16n8k16.row.col.f32.f16.f16.f32 "
                        "{%0,%1,%2,%3}, {%4,%5,%6,%7}, {%8,%9}, {%0,%1,%2,%3};"
                        : "+f"(acc[mt][nt][0]), "+f"(acc[mt][nt][1]),
                          "+f"(acc[mt][nt][2]), "+f"(acc[mt][nt][3])
                        : "r"(a[mt][0]), "r"(a[mt][1]), "r"(a[mt][2]), "r"(a[mt][3]),
                          "r"(b0), "r"(b1));
                }
            }
        }
        __syncthreads();
    }

    const int gr = lane >> 2;
    const int gc = (lane & 3) * 2;
#pragma unroll
    for (int mt = 0; mt < 4; mt++) {
#pragma unroll
        for (int nt = 0; nt < 4; nt++) {
            int col = n0 + wn + nt * 8 + gc;
            float2 bv = *(const float2*)&bias[col];
            int row0 = m0 + wm + mt * 16 + gr;
            float2 o0 = make_float2(acc[mt][nt][0] + bv.x, acc[mt][nt][1] + bv.y);
            float2 o1 = make_float2(acc[mt][nt][2] + bv.x, acc[mt][nt][3] + bv.y);
            *(float2*)&C[(size_t)row0 * 256 + col]       = o0;
            *(float2*)&C[(size_t)(row0 + 8) * 256 + col] = o1;
        }
    }
}

// ---------------------------------------------------------------------------
extern "C" void kernel_launch(void* const* d_in, const int* in_sizes, int n_in,
                              void* d_out, int out_size)
{
    const float* q        = (const float*)d_in[0];
    const float* map0     = (const float*)d_in[1];
    const float* map1     = (const float*)d_in[2];
    const float* base_ref = (const float*)d_in[3];
    const float* Wrd      = (const float*)d_in[4];
    const float* brd      = (const float*)d_in[5];
    const float* Woff     = (const float*)d_in[6];
    const float* boff     = (const float*)d_in[7];
    const float* Wattn    = (const float*)d_in[8];
    const float* battn    = (const float*)d_in[9];
    const float* Wout     = (const float*)d_in[10];
    const float* bout     = (const float*)d_in[11];
    float* out = (float*)d_out;

    prep_kernel<<<PREP_BLOCKS, 256>>>(Wrd, brd, Woff, boff, Wattn, battn,
                                      Wout, map0, map1);

    proj_hmma_kernel<<<NQ / 64, 256>>>(q);

    gather_fused_kernel<<<NQ / 16, 256>>>(base_ref);

    gemm_hmma_kernel<<<dim3(2, NQ / 128), 256>>>(bout, out);
}

// round 16
// speedup vs baseline: 1.0737x; 1.0737x over previous
#include <cuda_runtime.h>
#include <cuda_fp16.h>
#include <math.h>

#define Bn 4
#define Qn 8192
#define Dm 256
#define Lv 2
#define Pp 8
#define H0 128
#define W0 128
#define H1 64
#define W1 64
#define EPSV 1e-5f
#define NQ (Bn * Qn)          // 32768 total queries
#define MAP1_BASE (Bn * H0 * W0 * Dm)   // element offset of level-1 maps

// Scratch (device globals — no allocations allowed)
__device__ __half g_maps[Bn * (H0 * W0 + H1 * W1) * Dm];  // both maps, HWC fp16
__device__ __half g_pre16[NQ * Dm];            // pre-Wout accumulator (fp16)
__device__ __half g_Wout16[Dm * Dm];           // Wout in fp16
__device__ __half g_Wcat16h[256 * 64];         // packed proj weights hi, k-major [k][j]
__device__ __half g_Wcat16l[256 * 64];         // packed proj weights lo (residual)
__device__ float  g_bcatP[64];
__device__ float  g_dots[NQ * 64];             // projection outputs per query

__device__ __forceinline__ unsigned smem_u32(const void* p) {
    return (unsigned)__cvta_generic_to_shared(p);
}
__device__ __forceinline__ void cpa16(unsigned d, const void* s) {
    asm volatile("cp.async.cg.shared.global [%0], [%1], 16;" :: "r"(d), "l"(s));
}

// ---------------------------------------------------------------------------
// Kernel 0: merged packing.
// blocks 0..63: proj weights k-major split hi/lo. blocks 64..191: Wout fp16.
// ---------------------------------------------------------------------------
__global__ __launch_bounds__(256) void pack_all_kernel(
    const float* __restrict__ Wrd,  const float* __restrict__ brd,
    const float* __restrict__ Woff, const float* __restrict__ boff,
    const float* __restrict__ Wattn,const float* __restrict__ battn,
    const float* __restrict__ Wout)
{
    const int bx = blockIdx.x;
    const int t  = threadIdx.x;
    if (bx < 64) {
        int j = bx, k = t;
        float v = 0.f, bv = 0.f;
        if (j < 4)       { v = Wrd  [k * 4  + j];      bv = brd  [j]; }
        else if (j < 36) { v = Woff [k * 32 + (j-4)];  bv = boff [j-4]; }
        else if (j < 52) { v = Wattn[k * 16 + (j-36)]; bv = battn[j-36]; }
        __half hi = __float2half_rn(v);
        __half lo = __float2half_rn(v - __half2float(hi));
        g_Wcat16h[k * 64 + j] = hi;
        g_Wcat16l[k * 64 + j] = lo;
        if (k == 0) g_bcatP[j] = bv;
    } else {
        int idx = (bx - 64) * 256 + t;    // half2 index
        float2 v = ((const float2*)Wout)[idx];
        ((__half2*)g_Wout16)[idx] = __floats2half2_rn(v.x, v.y);
    }
}

// ---------------------------------------------------------------------------
// Kernel 1: both maps (B, D, HW) -> (B, HW, D) tiled transpose, fp32 -> fp16.
// ---------------------------------------------------------------------------
__global__ __launch_bounds__(256) void transpose_both_kernel(
    const float* __restrict__ map0, const float* __restrict__ map1)
{
    __shared__ float tile[64][33];

    const int bx    = blockIdx.x;
    const int level = (bx >= 512);
    const int HW    = level ? (H1 * W1) : (H0 * W0);
    const int hw0   = (level ? (bx - 512) : bx) * 32;
    const float* in = level ? map1 : map0;
    __half* out     = g_maps + (level ? MAP1_BASE : 0);

    const int d0  = blockIdx.y * 64;
    const int b   = blockIdx.z;
    const int tid  = threadIdx.x;
    const int tx   = tid & 31;
    const int ty   = tid >> 5;

    const float* inb = in + (size_t)b * Dm * HW;
    __half* outb = out + (size_t)b * HW * Dm;

#pragma unroll
    for (int i = 0; i < 8; i++) {
        int d = d0 + ty + 8 * i;
        tile[ty + 8 * i][tx] = inb[(size_t)d * HW + hw0 + tx];
    }
    __syncthreads();

#pragma unroll
    for (int i = 0; i < 4; i++) {
        int hw = ty + 8 * i;
        __half2 v = __floats2half2_rn(tile[2 * tx][hw], tile[2 * tx + 1][hw]);
        ((__half2*)(outb + (size_t)(hw0 + hw) * Dm + d0))[tx] = v;
    }
}

// ---------------------------------------------------------------------------
// Kernel 2: projection GEMM via split-fp16 HMMA (fp32-accurate), 2-stage
// pipeline. BM=64 (grid 512), BK=32 (8 iters), 8 warps = 4(m) x 2(n).
// ---------------------------------------------------------------------------
#define PAP 40        // A pitch in halves
#define PBP 72        // B pitch in halves

__global__ __launch_bounds__(256) void proj_hmma_kernel(const float* __restrict__ q)
{
    __shared__ __align__(16) __half Ah[2][64 * PAP];
    __shared__ __align__(16) __half Al[2][64 * PAP];
    __shared__ __align__(16) __half Bh[2][32 * PBP];
    __shared__ __align__(16) __half Bl[2][32 * PBP];

    const int tid  = threadIdx.x;
    const int wid  = tid >> 5;
    const int lane = tid & 31;
    const int m0 = blockIdx.x * 64;
    const int wm = (wid & 3) * 16;       // warp m offset
    const int wn = (wid >> 2) * 32;      // warp n offset

    const int lr = lane & 15;
    const int lc = (lane >> 4) * 8;

    const int ar = tid >> 3;             // 0..31 (+32 for second)
    const int ac = (tid & 7) * 4;
    const int br = tid >> 3;
    const int bc = (tid & 7) * 8;

    float4 ra0, ra1;
    float acc[4][4] = {};                // [nt][frag]

    // ---- prologue: tile 0 ----
    ra0 = *(const float4*)&q[(size_t)(m0 + ar) * 256 + ac];
    ra1 = *(const float4*)&q[(size_t)(m0 + ar + 32) * 256 + ac];
    cpa16(smem_u32(&Bh[0][br * PBP + bc]), &g_Wcat16h[br * 64 + bc]);
    cpa16(smem_u32(&Bl[0][br * PBP + bc]), &g_Wcat16l[br * 64 + bc]);
    asm volatile("cp.async.commit_group;");
    {
        float f0[4] = {ra0.x, ra0.y, ra0.z, ra0.w};
        float f1[4] = {ra1.x, ra1.y, ra1.z, ra1.w};
        __half h0[4], l0[4], h1[4], l1[4];
#pragma unroll
        for (int j = 0; j < 4; j++) {
            h0[j] = __float2half_rn(f0[j]);
            l0[j] = __float2half_rn(f0[j] - __half2float(h0[j]));
            h1[j] = __float2half_rn(f1[j]);
            l1[j] = __float2half_rn(f1[j] - __half2float(h1[j]));
        }
        int o0 = ar * PAP + ac;
        int o1 = (ar + 32) * PAP + ac;
        *(__half2*)&Ah[0][o0]     = __halves2half2(h0[0], h0[1]);
        *(__half2*)&Ah[0][o0 + 2] = __halves2half2(h0[2], h0[3]);
        *(__half2*)&Al[0][o0]     = __halves2half2(l0[0], l0[1]);
        *(__half2*)&Al[0][o0 + 2] = __halves2half2(l0[2], l0[3]);
        *(__half2*)&Ah[0][o1]     = __halves2half2(h1[0], h1[1]);
        *(__half2*)&Ah[0][o1 + 2] = __halves2half2(h1[2], h1[3]);
        *(__half2*)&Al[0][o1]     = __halves2half2(l1[0], l1[1]);
        *(__half2*)&Al[0][o1 + 2] = __halves2half2(l1[2], l1[3]);
    }
    asm volatile("cp.async.wait_group 0;");
    __syncthreads();

#pragma unroll 1
    for (int it = 0; it < 8; it++) {
        const int s = it & 1;

        if (it < 7) {
            const int k0n = (it + 1) * 32;
            ra0 = *(const float4*)&q[(size_t)(m0 + ar) * 256 + k0n + ac];
            ra1 = *(const float4*)&q[(size_t)(m0 + ar + 32) * 256 + k0n + ac];
            cpa16(smem_u32(&Bh[s ^ 1][br * PBP + bc]), &g_Wcat16h[(k0n + br) * 64 + bc]);
            cpa16(smem_u32(&Bl[s ^ 1][br * PBP + bc]), &g_Wcat16l[(k0n + br) * 64 + bc]);
            asm volatile("cp.async.commit_group;");
        }

#pragma unroll
        for (int kc = 0; kc < 2; kc++) {
            const int kk = kc * 16;
            unsigned a_h[4], a_l[4];
            {
                unsigned addr = smem_u32(&Ah[s][(wm + lr) * PAP + kk + lc]);
                asm volatile(
                    "ldmatrix.sync.aligned.m8n8.x4.shared.b16 {%0,%1,%2,%3}, [%4];"
                    : "=r"(a_h[0]), "=r"(a_h[1]), "=r"(a_h[2]), "=r"(a_h[3]) : "r"(addr));
                addr = smem_u32(&Al[s][(wm + lr) * PAP + kk + lc]);
                asm volatile(
                    "ldmatrix.sync.aligned.m8n8.x4.shared.b16 {%0,%1,%2,%3}, [%4];"
                    : "=r"(a_l[0]), "=r"(a_l[1]), "=r"(a_l[2]), "=r"(a_l[3]) : "r"(addr));
            }
            unsigned b_h[2][4], b_l[2][4];
#pragma unroll
            for (int ng = 0; ng < 2; ng++) {
                unsigned addr = smem_u32(&Bh[s][(kk + lr) * PBP + wn + ng * 16 + lc]);
                asm volatile(
                    "ldmatrix.sync.aligned.m8n8.x4.trans.shared.b16 {%0,%1,%2,%3}, [%4];"
                    : "=r"(b_h[ng][0]), "=r"(b_h[ng][1]), "=r"(b_h[ng][2]), "=r"(b_h[ng][3])
                    : "r"(addr));
                addr = smem_u32(&Bl[s][(kk + lr) * PBP + wn + ng * 16 + lc]);
                asm volatile(
                    "ldmatrix.sync.aligned.m8n8.x4.trans.shared.b16 {%0,%1,%2,%3}, [%4];"
                    : "=r"(b_l[ng][0]), "=r"(b_l[ng][1]), "=r"(b_l[ng][2]), "=r"(b_l[ng][3])
                    : "r"(addr));
            }
#pragma unroll
            for (int nt = 0; nt < 4; nt++) {
                unsigned bh0 = b_h[nt >> 1][(nt & 1) * 2 + 0];
                unsigned bh1 = b_h[nt >> 1][(nt & 1) * 2 + 1];
                unsigned bl0 = b_l[nt >> 1][(nt & 1) * 2 + 0];
                unsigned bl1 = b_l[nt >> 1][(nt & 1) * 2 + 1];
                asm volatile(
                    "mma.sync.aligned.m16n8k16.row.col.f32.f16.f16.f32 "
                    "{%0,%1,%2,%3}, {%4,%5,%6,%7}, {%8,%9}, {%0,%1,%2,%3};"
                    : "+f"(acc[nt][0]), "+f"(acc[nt][1]), "+f"(acc[nt][2]), "+f"(acc[nt][3])
                    : "r"(a_h[0]), "r"(a_h[1]), "r"(a_h[2]), "r"(a_h[3]), "r"(bh0), "r"(bh1));
                asm volatile(
                    "mma.sync.aligned.m16n8k16.row.col.f32.f16.f16.f32 "
                    "{%0,%1,%2,%3}, {%4,%5,%6,%7}, {%8,%9}, {%0,%1,%2,%3};"
                    : "+f"(acc[nt][0]), "+f"(acc[nt][1]), "+f"(acc[nt][2]), "+f"(acc[nt][3])
                    : "r"(a_h[0]), "r"(a_h[1]), "r"(a_h[2]), "r"(a_h[3]), "r"(bl0), "r"(bl1));
                asm volatile(
                    "mma.sync.aligned.m16n8k16.row.col.f32.f16.f16.f32 "
                    "{%0,%1,%2,%3}, {%4,%5,%6,%7}, {%8,%9}, {%0,%1,%2,%3};"
                    : "+f"(acc[nt][0]), "+f"(acc[nt][1]), "+f"(acc[nt][2]), "+f"(acc[nt][3])
                    : "r"(a_l[0]), "r"(a_l[1]), "r"(a_l[2]), "r"(a_l[3]), "r"(bh0), "r"(bh1));
            }
        }

        if (it < 7) {
            const int sn = s ^ 1;
            float f0[4] = {ra0.x, ra0.y, ra0.z, ra0.w};
            float f1[4] = {ra1.x, ra1.y, ra1.z, ra1.w};
            __half h0[4], l0[4], h1[4], l1[4];
#pragma unroll
            for (int j = 0; j < 4; j++) {
                h0[j] = __float2half_rn(f0[j]);
                l0[j] = __float2half_rn(f0[j] - __half2float(h0[j]));
                h1[j] = __float2half_rn(f1[j]);
                l1[j] = __float2half_rn(f1[j] - __half2float(h1[j]));
            }
            int o0 = ar * PAP + ac;
            int o1 = (ar + 32) * PAP + ac;
            *(__half2*)&Ah[sn][o0]     = __halves2half2(h0[0], h0[1]);
            *(__half2*)&Ah[sn][o0 + 2] = __halves2half2(h0[2], h0[3]);
            *(__half2*)&Al[sn][o0]     = __halves2half2(l0[0], l0[1]);
            *(__half2*)&Al[sn][o0 + 2] = __halves2half2(l0[2], l0[3]);
            *(__half2*)&Ah[sn][o1]     = __halves2half2(h1[0], h1[1]);
            *(__half2*)&Ah[sn][o1 + 2] = __halves2half2(h1[2], h1[3]);
            *(__half2*)&Al[sn][o1]     = __halves2half2(l1[0], l1[1]);
            *(__half2*)&Al[sn][o1 + 2] = __halves2half2(l1[2], l1[3]);
            asm volatile("cp.async.wait_group 0;");
        }
        __syncthreads();
    }

    // epilogue: + bias -> g_dots (fp32)
    const int gr = lane >> 2;
    const int gc = (lane & 3) * 2;
#pragma unroll
    for (int nt = 0; nt < 4; nt++) {
        int col = wn + nt * 8 + gc;
        float2 bv = *(const float2*)&g_bcatP[col];
        int row0 = m0 + wm + gr;
        float2 o0 = make_float2(acc[nt][0] + bv.x, acc[nt][1] + bv.y);
        float2 o1 = make_float2(acc[nt][2] + bv.x, acc[nt][3] + bv.y);
        *(float2*)&g_dots[(size_t)row0 * 64 + col]       = o0;
        *(float2*)&g_dots[(size_t)(row0 + 8) * 64 + col] = o1;
    }
}

// ---------------------------------------------------------------------------
// Kernel 3: FUSED coords + softmax + gather. 16 queries per block.
// R12-style gather: int element offsets (level base folded), float4 corner
// weights converted to half2 inline per point (38-reg configuration).
// ---------------------------------------------------------------------------
__global__ __launch_bounds__(256) void gather_fused_kernel(
    const float* __restrict__ base_ref)
{
    __shared__ int4   soff[16][16];    // element offsets of 4 corners
    __shared__ float4 scw [16][16];    // corner weights (attn folded), fp32

    const int tid = threadIdx.x;
    const int q0  = blockIdx.x * 16;

    // ---------- Phase 1: coordinates + softmax ----------
    {
        const int qq = tid >> 4;          // query within block (0..15)
        const int p  = tid & 15;          // point (0..15)
        const int qidx = q0 + qq;
        const int b = qidx >> 13;         // Qn = 8192

        const float* dots = &g_dots[(size_t)qidx * 64];

        float logit = dots[36 + p];
        float m = logit;
#pragma unroll
        for (int o = 8; o; o >>= 1)
            m = fmaxf(m, __shfl_xor_sync(0xffffffffu, m, o));
        float e = expf(logit - m);
        float esum = e;
#pragma unroll
        for (int o = 8; o; o >>= 1)
            esum += __shfl_xor_sync(0xffffffffu, esum, o);
        float wattn = e / esum;

        const int l  = p >> 3;
        const int pp = p & 7;
        const int Wl = l ? W1 : W0;
        const int Hl = l ? H1 : H0;

        float bx = base_ref[(b * Lv + l) * 2 + 0];
        float by = base_ref[(b * Lv + l) * 2 + 1];
        bx = fminf(fmaxf(bx, EPSV), 1.f - EPSV);
        by = fminf(fmaxf(by, EPSV), 1.f - EPSV);
        float lbx = logf(bx / (1.f - bx));
        float lby = logf(by / (1.f - by));
        float rx = 1.f / (1.f + expf(-(lbx + dots[l * 2 + 0])));
        float ry = 1.f / (1.f + expf(-(lby + dots[l * 2 + 1])));

        float ox = dots[4 + l * 16 + pp * 2 + 0];
        float oy = dots[4 + l * 16 + pp * 2 + 1];
        float lx = rx + ox / (float)Wl;
        float ly = ry + oy / (float)Hl;
        if (l == 1) ly = ly - floorf(ly);   // jnp.remainder(ly, 1.0)

        float x = lx * (float)Wl - 0.5f;
        float y = ly * (float)Hl - 0.5f;
        x = fminf(fmaxf(x, 0.f), (float)(Wl - 1));
        y = fminf(fmaxf(y, 0.f), (float)(Hl - 1));
        float x0f = floorf(x), y0f = floorf(y);
        float wx = x - x0f, wy = y - y0f;
        int x0 = (int)x0f, y0 = (int)y0f;
        int x1 = min(x0 + 1, Wl - 1);
        int y1 = min(y0 + 1, Hl - 1);
        int base = (l ? MAP1_BASE : 0) + b * Hl * Wl * Dm;

        int4 off;   // element offsets
        off.x = base + (y0 * Wl + x0) * Dm;
        off.y = base + (y0 * Wl + x1) * Dm;
        off.z = base + (y1 * Wl + x0) * Dm;
        off.w = base + (y1 * Wl + x1) * Dm;
        soff[qq][p] = off;

        float4 cw;
        cw.x = (1.f - wx) * (1.f - wy) * wattn;
        cw.y = wx * (1.f - wy) * wattn;
        cw.z = (1.f - wx) * wy * wattn;
        cw.w = wx * wy * wattn;
        scw[qq][p] = cw;
    }
    __syncthreads();

    // ---------- Phase 2: gather (fp16 HFMA2 interp, fp32 accumulate) ----------
    const int w    = tid >> 5;
    const int lane = tid & 31;
    const int co   = lane * 8;

#pragma unroll
    for (int h = 0; h < 2; h++) {
        const int qq = 2 * w + h;
        float acc[8] = {};

#pragma unroll
        for (int p = 0; p < 16; p++) {
            const int4   o  = soff[qq][p];
            const float4 cw = scw[qq][p];

            __half2 c00 = __float2half2_rn(cw.x);
            __half2 c01 = __float2half2_rn(cw.y);
            __half2 c10 = __float2half2_rn(cw.z);
            __half2 c11 = __float2half2_rn(cw.w);

            float4 r00 = __ldg((const float4*)(g_maps + o.x + co));
            float4 r01 = __ldg((const float4*)(g_maps + o.y + co));
            float4 r10 = __ldg((const float4*)(g_maps + o.z + co));
            float4 r11 = __ldg((const float4*)(g_maps + o.w + co));
            const __half2* h00 = (const __half2*)&r00;
            const __half2* h01 = (const __half2*)&r01;
            const __half2* h10 = (const __half2*)&r10;
            const __half2* h11 = (const __half2*)&r11;

#pragma unroll
            for (int j = 0; j < 4; j++) {
                __half2 t = __hmul2(c00, h00[j]);
                t = __hfma2(c01, h01[j], t);
                t = __hfma2(c10, h10[j], t);
                t = __hfma2(c11, h11[j], t);
                float2 f = __half22float2(t);
                acc[2 * j + 0] += f.x;
                acc[2 * j + 1] += f.y;
            }
        }

        __half2 hv[4];
#pragma unroll
        for (int j = 0; j < 4; j++)
            hv[j] = __floats2half2_rn(acc[2 * j], acc[2 * j + 1]);
        *(uint4*)&g_pre16[(size_t)(q0 + qq) * 256 + co] = *(uint4*)hv;
    }
}

// ---------------------------------------------------------------------------
// Kernel 4: C = g_pre16(M,256) @ Wout16(256,256) + bout  via HMMA m16n8k16.
// ---------------------------------------------------------------------------
#define HAPITCH 40
#define HBPITCH 136

__global__ __launch_bounds__(256) void gemm_hmma_kernel(
    const float* __restrict__ bias, float* __restrict__ C)
{
    __shared__ __align__(16) __half As[2][128 * HAPITCH];
    __shared__ __align__(16) __half Bs[2][32 * HBPITCH];

    const int tid  = threadIdx.x;
    const int wid  = tid >> 5;
    const int lane = tid & 31;
    const int m0 = blockIdx.y * 128;
    const int n0 = blockIdx.x * 128;
    const int wm = (wid & 1) * 64;
    const int wn = (wid >> 1) * 32;

    const int ara = tid >> 2;
    const int aca = (tid & 3) * 8;
    const int brb = tid >> 4;
    const int bcb = (tid & 15) * 8;

    float acc[4][4][4] = {};

    const int lr = lane & 15;
    const int lc = (lane >> 4) * 8;

    {
        const int k0 = 0;
        cpa16(smem_u32(&As[0][ara * HAPITCH + aca]),
              &g_pre16[(size_t)(m0 + ara) * 256 + k0 + aca]);
        cpa16(smem_u32(&As[0][(ara + 64) * HAPITCH + aca]),
              &g_pre16[(size_t)(m0 + ara + 64) * 256 + k0 + aca]);
        cpa16(smem_u32(&Bs[0][brb * HBPITCH + bcb]),
              &g_Wout16[(size_t)(k0 + brb) * 256 + n0 + bcb]);
        cpa16(smem_u32(&Bs[0][(brb + 16) * HBPITCH + bcb]),
              &g_Wout16[(size_t)(k0 + brb + 16) * 256 + n0 + bcb]);
        asm volatile("cp.async.commit_group;");
    }

#pragma unroll
    for (int it = 0; it < 8; it++) {
        if (it + 1 < 8) {
            const int k0 = (it + 1) * 32;
            const int s = (it + 1) & 1;
            cpa16(smem_u32(&As[s][ara * HAPITCH + aca]),
                  &g_pre16[(size_t)(m0 + ara) * 256 + k0 + aca]);
            cpa16(smem_u32(&As[s][(ara + 64) * HAPITCH + aca]),
                  &g_pre16[(size_t)(m0 + ara + 64) * 256 + k0 + aca]);
            cpa16(smem_u32(&Bs[s][brb * HBPITCH + bcb]),
                  &g_Wout16[(size_t)(k0 + brb) * 256 + n0 + bcb]);
            cpa16(smem_u32(&Bs[s][(brb + 16) * HBPITCH + bcb]),
                  &g_Wout16[(size_t)(k0 + brb + 16) * 256 + n0 + bcb]);
            asm volatile("cp.async.commit_group;");
            asm volatile("cp.async.wait_group 1;");
        } else {
            asm volatile("cp.async.wait_group 0;");
        }
        __syncthreads();

        const int s = it & 1;
#pragma unroll
        for (int kk = 0; kk < 32; kk += 16) {
            unsigned a[4][4];
#pragma unroll
            for (int mt = 0; mt < 4; mt++) {
                unsigned addr = smem_u32(&As[s][(wm + mt * 16 + lr) * HAPITCH + kk + lc]);
                asm volatile(
                    "ldmatrix.sync.aligned.m8n8.x4.shared.b16 {%0,%1,%2,%3}, [%4];"
                    : "=r"(a[mt][0]), "=r"(a[mt][1]), "=r"(a[mt][2]), "=r"(a[mt][3])
                    : "r"(addr));
            }
            unsigned b[2][4];
#pragma unroll
            for (int ng = 0; ng < 2; ng++) {
                unsigned addr = smem_u32(&Bs[s][(kk + lr) * HBPITCH + wn + ng * 16 + lc]);
                asm volatile(
                    "ldmatrix.sync.aligned.m8n8.x4.trans.shared.b16 {%0,%1,%2,%3}, [%4];"
                    : "=r"(b[ng][0]), "=r"(b[ng][1]), "=r"(b[ng][2]), "=r"(b[ng][3])
                    : "r"(addr));
            }
#pragma unroll
            for (int mt = 0; mt < 4; mt++) {
#pragma unroll
                for (int nt = 0; nt < 4; nt++) {
                    unsigned b0 = b[nt >> 1][(nt & 1) * 2 + 0];
                    unsigned b1 = b[nt >> 1][(nt & 1) * 2 + 1];
                    asm volatile(
                        "mma.sync.aligned.m16n8k16.row.col.f32.f16.f16.f32 "
                        "{%0,%1,%2,%3}, {%4,%5,%6,%7}, {%8,%9}, {%0,%1,%2,%3};"
                        : "+f"(acc[mt][nt][0]), "+f"(acc[mt][nt][1]),
                          "+f"(acc[mt][nt][2]), "+f"(acc[mt][nt][3])
                        : "r"(a[mt][0]), "r"(a[mt][1]), "r"(a[mt][2]), "r"(a[mt][3]),
                          "r"(b0), "r"(b1));
                }
            }
        }
        __syncthreads();
    }

    const int gr = lane >> 2;
    const int gc = (lane & 3) * 2;
#pragma unroll
    for (int mt = 0; mt < 4; mt++) {
#pragma unroll
        for (int nt = 0; nt < 4; nt++) {
            int col = n0 + wn + nt * 8 + gc;
            float2 bv = *(const float2*)&bias[col];
            int row0 = m0 + wm + mt * 16 + gr;
            float2 o0 = make_float2(acc[mt][nt][0] + bv.x, acc[mt][nt][1] + bv.y);
            float2 o1 = make_float2(acc[mt][nt][2] + bv.x, acc[mt][nt][3] + bv.y);
            *(float2*)&C[(size_t)row0 * 256 + col]       = o0;
            *(float2*)&C[(size_t)(row0 + 8) * 256 + col] = o1;
        }
    }
}

// ---------------------------------------------------------------------------
extern "C" void kernel_launch(void* const* d_in, const int* in_sizes, int n_in,
                              void* d_out, int out_size)
{
    const float* q        = (const float*)d_in[0];
    const float* map0     = (const float*)d_in[1];
    const float* map1     = (const float*)d_in[2];
    const float* base_ref = (const float*)d_in[3];
    const float* Wrd      = (const float*)d_in[4];
    const float* brd      = (const float*)d_in[5];
    const float* Woff     = (const float*)d_in[6];
    const float* boff     = (const float*)d_in[7];
    const float* Wattn    = (const float*)d_in[8];
    const float* battn    = (const float*)d_in[9];
    const float* Wout     = (const float*)d_in[10];
    const float* bout     = (const float*)d_in[11];
    float* out = (float*)d_out;

    pack_all_kernel<<<192, 256>>>(Wrd, brd, Woff, boff, Wattn, battn, Wout);

    transpose_both_kernel<<<dim3(512 + 128, Dm / 64, Bn), 256>>>(map0, map1);

    proj_hmma_kernel<<<NQ / 64, 256>>>(q);

    gather_fused_kernel<<<NQ / 16, 256>>>(base_ref);

    gemm_hmma_kernel<<<dim3(2, NQ / 128), 256>>>(bout, out);
}

// round 17
// speedup vs baseline: 1.0827x; 1.0084x over previous
#include <cuda_runtime.h>
#include <cuda_fp16.h>
#include <math.h>

#define Bn 4
#define Qn 8192
#define Dm 256
#define Lv 2
#define Pp 8
#define H0 128
#define W0 128
#define H1 64
#define W1 64
#define EPSV 1e-5f
#define NQ (Bn * Qn)          // 32768 total queries
#define MAP1_BASE (Bn * H0 * W0 * Dm)   // element offset of level-1 maps

// Scratch (device globals — no allocations allowed)
__device__ __half g_maps[Bn * (H0 * W0 + H1 * W1) * Dm];  // both maps, HWC fp16
__device__ __half g_pre16[NQ * Dm];            // pre-Wout accumulator (fp16)
__device__ __half g_Wout16[Dm * Dm];           // Wout in fp16
__device__ __half g_Wcat16h[256 * 64];         // packed proj weights hi, k-major [k][j]
__device__ __half g_Wcat16l[256 * 64];         // packed proj weights lo (residual)
__device__ float  g_bcatP[64];
__device__ float  g_dots[NQ * 64];             // projection outputs per query

__device__ __forceinline__ unsigned smem_u32(const void* p) {
    return (unsigned)__cvta_generic_to_shared(p);
}
__device__ __forceinline__ void cpa16(unsigned d, const void* s) {
    asm volatile("cp.async.cg.shared.global [%0], [%1], 16;" :: "r"(d), "l"(s));
}

// ---------------------------------------------------------------------------
// Kernel 0: merged packing.
// ---------------------------------------------------------------------------
__global__ __launch_bounds__(256) void pack_all_kernel(
    const float* __restrict__ Wrd,  const float* __restrict__ brd,
    const float* __restrict__ Woff, const float* __restrict__ boff,
    const float* __restrict__ Wattn,const float* __restrict__ battn,
    const float* __restrict__ Wout)
{
    const int bx = blockIdx.x;
    const int t  = threadIdx.x;
    if (bx < 64) {
        int j = bx, k = t;
        float v = 0.f, bv = 0.f;
        if (j < 4)       { v = Wrd  [k * 4  + j];      bv = brd  [j]; }
        else if (j < 36) { v = Woff [k * 32 + (j-4)];  bv = boff [j-4]; }
        else if (j < 52) { v = Wattn[k * 16 + (j-36)]; bv = battn[j-36]; }
        __half hi = __float2half_rn(v);
        __half lo = __float2half_rn(v - __half2float(hi));
        g_Wcat16h[k * 64 + j] = hi;
        g_Wcat16l[k * 64 + j] = lo;
        if (k == 0) g_bcatP[j] = bv;
    } else {
        int idx = (bx - 64) * 256 + t;    // half2 index
        float2 v = ((const float2*)Wout)[idx];
        ((__half2*)g_Wout16)[idx] = __floats2half2_rn(v.x, v.y);
    }
}

// ---------------------------------------------------------------------------
// Kernel 1: both maps (B, D, HW) -> (B, HW, D) tiled transpose, fp32 -> fp16.
// ---------------------------------------------------------------------------
__global__ __launch_bounds__(256) void transpose_both_kernel(
    const float* __restrict__ map0, const float* __restrict__ map1)
{
    __shared__ float tile[64][33];

    const int bx    = blockIdx.x;
    const int level = (bx >= 512);
    const int HW    = level ? (H1 * W1) : (H0 * W0);
    const int hw0   = (level ? (bx - 512) : bx) * 32;
    const float* in = level ? map1 : map0;
    __half* out     = g_maps + (level ? MAP1_BASE : 0);

    const int d0  = blockIdx.y * 64;
    const int b   = blockIdx.z;
    const int tid  = threadIdx.x;
    const int tx   = tid & 31;
    const int ty   = tid >> 5;

    const float* inb = in + (size_t)b * Dm * HW;
    __half* outb = out + (size_t)b * HW * Dm;

#pragma unroll
    for (int i = 0; i < 8; i++) {
        int d = d0 + ty + 8 * i;
        tile[ty + 8 * i][tx] = inb[(size_t)d * HW + hw0 + tx];
    }
    __syncthreads();

#pragma unroll
    for (int i = 0; i < 4; i++) {
        int hw = ty + 8 * i;
        __half2 v = __floats2half2_rn(tile[2 * tx][hw], tile[2 * tx + 1][hw]);
        ((__half2*)(outb + (size_t)(hw0 + hw) * Dm + d0))[tx] = v;
    }
}

// ---------------------------------------------------------------------------
// Kernel 2: projection GEMM via split-fp16 HMMA (fp32-accurate), 2-stage
// pipeline. (unchanged from R14/R16)
// ---------------------------------------------------------------------------
#define PAP 40        // A pitch in halves
#define PBP 72        // B pitch in halves

__global__ __launch_bounds__(256) void proj_hmma_kernel(const float* __restrict__ q)
{
    __shared__ __align__(16) __half Ah[2][64 * PAP];
    __shared__ __align__(16) __half Al[2][64 * PAP];
    __shared__ __align__(16) __half Bh[2][32 * PBP];
    __shared__ __align__(16) __half Bl[2][32 * PBP];

    const int tid  = threadIdx.x;
    const int wid  = tid >> 5;
    const int lane = tid & 31;
    const int m0 = blockIdx.x * 64;
    const int wm = (wid & 3) * 16;
    const int wn = (wid >> 2) * 32;

    const int lr = lane & 15;
    const int lc = (lane >> 4) * 8;

    const int ar = tid >> 3;
    const int ac = (tid & 7) * 4;
    const int br = tid >> 3;
    const int bc = (tid & 7) * 8;

    float4 ra0, ra1;
    float acc[4][4] = {};

    ra0 = *(const float4*)&q[(size_t)(m0 + ar) * 256 + ac];
    ra1 = *(const float4*)&q[(size_t)(m0 + ar + 32) * 256 + ac];
    cpa16(smem_u32(&Bh[0][br * PBP + bc]), &g_Wcat16h[br * 64 + bc]);
    cpa16(smem_u32(&Bl[0][br * PBP + bc]), &g_Wcat16l[br * 64 + bc]);
    asm volatile("cp.async.commit_group;");
    {
        float f0[4] = {ra0.x, ra0.y, ra0.z, ra0.w};
        float f1[4] = {ra1.x, ra1.y, ra1.z, ra1.w};
        __half h0[4], l0[4], h1[4], l1[4];
#pragma unroll
        for (int j = 0; j < 4; j++) {
            h0[j] = __float2half_rn(f0[j]);
            l0[j] = __float2half_rn(f0[j] - __half2float(h0[j]));
            h1[j] = __float2half_rn(f1[j]);
            l1[j] = __float2half_rn(f1[j] - __half2float(h1[j]));
        }
        int o0 = ar * PAP + ac;
        int o1 = (ar + 32) * PAP + ac;
        *(__half2*)&Ah[0][o0]     = __halves2half2(h0[0], h0[1]);
        *(__half2*)&Ah[0][o0 + 2] = __halves2half2(h0[2], h0[3]);
        *(__half2*)&Al[0][o0]     = __halves2half2(l0[0], l0[1]);
        *(__half2*)&Al[0][o0 + 2] = __halves2half2(l0[2], l0[3]);
        *(__half2*)&Ah[0][o1]     = __halves2half2(h1[0], h1[1]);
        *(__half2*)&Ah[0][o1 + 2] = __halves2half2(h1[2], h1[3]);
        *(__half2*)&Al[0][o1]     = __halves2half2(l1[0], l1[1]);
        *(__half2*)&Al[0][o1 + 2] = __halves2half2(l1[2], l1[3]);
    }
    asm volatile("cp.async.wait_group 0;");
    __syncthreads();

#pragma unroll 1
    for (int it = 0; it < 8; it++) {
        const int s = it & 1;

        if (it < 7) {
            const int k0n = (it + 1) * 32;
            ra0 = *(const float4*)&q[(size_t)(m0 + ar) * 256 + k0n + ac];
            ra1 = *(const float4*)&q[(size_t)(m0 + ar + 32) * 256 + k0n + ac];
            cpa16(smem_u32(&Bh[s ^ 1][br * PBP + bc]), &g_Wcat16h[(k0n + br) * 64 + bc]);
            cpa16(smem_u32(&Bl[s ^ 1][br * PBP + bc]), &g_Wcat16l[(k0n + br) * 64 + bc]);
            asm volatile("cp.async.commit_group;");
        }

#pragma unroll
        for (int kc = 0; kc < 2; kc++) {
            const int kk = kc * 16;
            unsigned a_h[4], a_l[4];
            {
                unsigned addr = smem_u32(&Ah[s][(wm + lr) * PAP + kk + lc]);
                asm volatile(
                    "ldmatrix.sync.aligned.m8n8.x4.shared.b16 {%0,%1,%2,%3}, [%4];"
                    : "=r"(a_h[0]), "=r"(a_h[1]), "=r"(a_h[2]), "=r"(a_h[3]) : "r"(addr));
                addr = smem_u32(&Al[s][(wm + lr) * PAP + kk + lc]);
                asm volatile(
                    "ldmatrix.sync.aligned.m8n8.x4.shared.b16 {%0,%1,%2,%3}, [%4];"
                    : "=r"(a_l[0]), "=r"(a_l[1]), "=r"(a_l[2]), "=r"(a_l[3]) : "r"(addr));
            }
            unsigned b_h[2][4], b_l[2][4];
#pragma unroll
            for (int ng = 0; ng < 2; ng++) {
                unsigned addr = smem_u32(&Bh[s][(kk + lr) * PBP + wn + ng * 16 + lc]);
                asm volatile(
                    "ldmatrix.sync.aligned.m8n8.x4.trans.shared.b16 {%0,%1,%2,%3}, [%4];"
                    : "=r"(b_h[ng][0]), "=r"(b_h[ng][1]), "=r"(b_h[ng][2]), "=r"(b_h[ng][3])
                    : "r"(addr));
                addr = smem_u32(&Bl[s][(kk + lr) * PBP + wn + ng * 16 + lc]);
                asm volatile(
                    "ldmatrix.sync.aligned.m8n8.x4.trans.shared.b16 {%0,%1,%2,%3}, [%4];"
                    : "=r"(b_l[ng][0]), "=r"(b_l[ng][1]), "=r"(b_l[ng][2]), "=r"(b_l[ng][3])
                    : "r"(addr));
            }
#pragma unroll
            for (int nt = 0; nt < 4; nt++) {
                unsigned bh0 = b_h[nt >> 1][(nt & 1) * 2 + 0];
                unsigned bh1 = b_h[nt >> 1][(nt & 1) * 2 + 1];
                unsigned bl0 = b_l[nt >> 1][(nt & 1) * 2 + 0];
                unsigned bl1 = b_l[nt >> 1][(nt & 1) * 2 + 1];
                asm volatile(
                    "mma.sync.aligned.m16n8k16.row.col.f32.f16.f16.f32 "
                    "{%0,%1,%2,%3}, {%4,%5,%6,%7}, {%8,%9}, {%0,%1,%2,%3};"
                    : "+f"(acc[nt][0]), "+f"(acc[nt][1]), "+f"(acc[nt][2]), "+f"(acc[nt][3])
                    : "r"(a_h[0]), "r"(a_h[1]), "r"(a_h[2]), "r"(a_h[3]), "r"(bh0), "r"(bh1));
                asm volatile(
                    "mma.sync.aligned.m16n8k16.row.col.f32.f16.f16.f32 "
                    "{%0,%1,%2,%3}, {%4,%5,%6,%7}, {%8,%9}, {%0,%1,%2,%3};"
                    : "+f"(acc[nt][0]), "+f"(acc[nt][1]), "+f"(acc[nt][2]), "+f"(acc[nt][3])
                    : "r"(a_h[0]), "r"(a_h[1]), "r"(a_h[2]), "r"(a_h[3]), "r"(bl0), "r"(bl1));
                asm volatile(
                    "mma.sync.aligned.m16n8k16.row.col.f32.f16.f16.f32 "
                    "{%0,%1,%2,%3}, {%4,%5,%6,%7}, {%8,%9}, {%0,%1,%2,%3};"
                    : "+f"(acc[nt][0]), "+f"(acc[nt][1]), "+f"(acc[nt][2]), "+f"(acc[nt][3])
                    : "r"(a_l[0]), "r"(a_l[1]), "r"(a_l[2]), "r"(a_l[3]), "r"(bh0), "r"(bh1));
            }
        }

        if (it < 7) {
            const int sn = s ^ 1;
            float f0[4] = {ra0.x, ra0.y, ra0.z, ra0.w};
            float f1[4] = {ra1.x, ra1.y, ra1.z, ra1.w};
            __half h0[4], l0[4], h1[4], l1[4];
#pragma unroll
            for (int j = 0; j < 4; j++) {
                h0[j] = __float2half_rn(f0[j]);
                l0[j] = __float2half_rn(f0[j] - __half2float(h0[j]));
                h1[j] = __float2half_rn(f1[j]);
                l1[j] = __float2half_rn(f1[j] - __half2float(h1[j]));
            }
            int o0 = ar * PAP + ac;
            int o1 = (ar + 32) * PAP + ac;
            *(__half2*)&Ah[sn][o0]     = __halves2half2(h0[0], h0[1]);
            *(__half2*)&Ah[sn][o0 + 2] = __halves2half2(h0[2], h0[3]);
            *(__half2*)&Al[sn][o0]     = __halves2half2(l0[0], l0[1]);
            *(__half2*)&Al[sn][o0 + 2] = __halves2half2(l0[2], l0[3]);
            *(__half2*)&Ah[sn][o1]     = __halves2half2(h1[0], h1[1]);
            *(__half2*)&Ah[sn][o1 + 2] = __halves2half2(h1[2], h1[3]);
            *(__half2*)&Al[sn][o1]     = __halves2half2(l1[0], l1[1]);
            *(__half2*)&Al[sn][o1 + 2] = __halves2half2(l1[2], l1[3]);
            asm volatile("cp.async.wait_group 0;");
        }
        __syncthreads();
    }

    const int gr = lane >> 2;
    const int gc = (lane & 3) * 2;
#pragma unroll
    for (int nt = 0; nt < 4; nt++) {
        int col = wn + nt * 8 + gc;
        float2 bv = *(const float2*)&g_bcatP[col];
        int row0 = m0 + wm + gr;
        float2 o0 = make_float2(acc[nt][0] + bv.x, acc[nt][1] + bv.y);
        float2 o1 = make_float2(acc[nt][2] + bv.x, acc[nt][3] + bv.y);
        *(float2*)&g_dots[(size_t)row0 * 64 + col]       = o0;
        *(float2*)&g_dots[(size_t)(row0 + 8) * 64 + col] = o1;
    }
}

// ---------------------------------------------------------------------------
// Kernel 3: FUSED coords + softmax + gather. 16 queries per block.
// Gather: half2 accumulation over 4-point groups, fp32 flush every 4 points.
// ---------------------------------------------------------------------------
__global__ __launch_bounds__(256) void gather_fused_kernel(
    const float* __restrict__ base_ref)
{
    __shared__ int4   soff[16][16];    // element offsets of 4 corners
    __shared__ float4 scw [16][16];    // corner weights (attn folded), fp32

    const int tid = threadIdx.x;
    const int q0  = blockIdx.x * 16;

    // ---------- Phase 1: coordinates + softmax ----------
    {
        const int qq = tid >> 4;
        const int p  = tid & 15;
        const int qidx = q0 + qq;
        const int b = qidx >> 13;         // Qn = 8192

        const float* dots = &g_dots[(size_t)qidx * 64];

        float logit = dots[36 + p];
        float m = logit;
#pragma unroll
        for (int o = 8; o; o >>= 1)
            m = fmaxf(m, __shfl_xor_sync(0xffffffffu, m, o));
        float e = expf(logit - m);
        float esum = e;
#pragma unroll
        for (int o = 8; o; o >>= 1)
            esum += __shfl_xor_sync(0xffffffffu, esum, o);
        float wattn = e / esum;

        const int l  = p >> 3;
        const int pp = p & 7;
        const int Wl = l ? W1 : W0;
        const int Hl = l ? H1 : H0;

        float bx = base_ref[(b * Lv + l) * 2 + 0];
        float by = base_ref[(b * Lv + l) * 2 + 1];
        bx = fminf(fmaxf(bx, EPSV), 1.f - EPSV);
        by = fminf(fmaxf(by, EPSV), 1.f - EPSV);
        float lbx = logf(bx / (1.f - bx));
        float lby = logf(by / (1.f - by));
        float rx = 1.f / (1.f + expf(-(lbx + dots[l * 2 + 0])));
        float ry = 1.f / (1.f + expf(-(lby + dots[l * 2 + 1])));

        float ox = dots[4 + l * 16 + pp * 2 + 0];
        float oy = dots[4 + l * 16 + pp * 2 + 1];
        float lx = rx + ox / (float)Wl;
        float ly = ry + oy / (float)Hl;
        if (l == 1) ly = ly - floorf(ly);   // jnp.remainder(ly, 1.0)

        float x = lx * (float)Wl - 0.5f;
        float y = ly * (float)Hl - 0.5f;
        x = fminf(fmaxf(x, 0.f), (float)(Wl - 1));
        y = fminf(fmaxf(y, 0.f), (float)(Hl - 1));
        float x0f = floorf(x), y0f = floorf(y);
        float wx = x - x0f, wy = y - y0f;
        int x0 = (int)x0f, y0 = (int)y0f;
        int x1 = min(x0 + 1, Wl - 1);
        int y1 = min(y0 + 1, Hl - 1);
        int base = (l ? MAP1_BASE : 0) + b * Hl * Wl * Dm;

        int4 off;
        off.x = base + (y0 * Wl + x0) * Dm;
        off.y = base + (y0 * Wl + x1) * Dm;
        off.z = base + (y1 * Wl + x0) * Dm;
        off.w = base + (y1 * Wl + x1) * Dm;
        soff[qq][p] = off;

        float4 cw;
        cw.x = (1.f - wx) * (1.f - wy) * wattn;
        cw.y = wx * (1.f - wy) * wattn;
        cw.z = (1.f - wx) * wy * wattn;
        cw.w = wx * wy * wattn;
        scw[qq][p] = cw;
    }
    __syncthreads();

    // ---------- Phase 2: gather ----------
    const int w    = tid >> 5;
    const int lane = tid & 31;
    const int co   = lane * 8;

#pragma unroll
    for (int h = 0; h < 2; h++) {
        const int qq = 2 * w + h;
        float acc[8] = {};
        __half2 hacc[4] = {__half2(0, 0), __half2(0, 0), __half2(0, 0), __half2(0, 0)};

#pragma unroll
        for (int p = 0; p < 16; p++) {
            const int4   o  = soff[qq][p];
            const float4 cw = scw[qq][p];

            __half2 c00 = __float2half2_rn(cw.x);
            __half2 c01 = __float2half2_rn(cw.y);
            __half2 c10 = __float2half2_rn(cw.z);
            __half2 c11 = __float2half2_rn(cw.w);

            float4 r00 = __ldg((const float4*)(g_maps + o.x + co));
            float4 r01 = __ldg((const float4*)(g_maps + o.y + co));
            float4 r10 = __ldg((const float4*)(g_maps + o.z + co));
            float4 r11 = __ldg((const float4*)(g_maps + o.w + co));
            const __half2* h00 = (const __half2*)&r00;
            const __half2* h01 = (const __half2*)&r01;
            const __half2* h10 = (const __half2*)&r10;
            const __half2* h11 = (const __half2*)&r11;

#pragma unroll
            for (int j = 0; j < 4; j++) {
                hacc[j] = __hfma2(c00, h00[j], hacc[j]);
                hacc[j] = __hfma2(c01, h01[j], hacc[j]);
                hacc[j] = __hfma2(c10, h10[j], hacc[j]);
                hacc[j] = __hfma2(c11, h11[j], hacc[j]);
            }

            if ((p & 3) == 3) {          // flush every 4 points
#pragma unroll
                for (int j = 0; j < 4; j++) {
                    float2 f = __half22float2(hacc[j]);
                    acc[2 * j + 0] += f.x;
                    acc[2 * j + 1] += f.y;
                    hacc[j] = __half2(0, 0);
                }
            }
        }

        __half2 hv[4];
#pragma unroll
        for (int j = 0; j < 4; j++)
            hv[j] = __floats2half2_rn(acc[2 * j], acc[2 * j + 1]);
        *(uint4*)&g_pre16[(size_t)(q0 + qq) * 256 + co] = *(uint4*)hv;
    }
}

// ---------------------------------------------------------------------------
// Kernel 4: C = g_pre16(M,256) @ Wout16(256,256) + bout via HMMA m16n8k16.
// BM=64, BN=128 (grid 2 x 512); warp tile 32x32 (acc 32 regs) for occupancy.
// ---------------------------------------------------------------------------
#define HAPITCH 40
#define HBPITCH 136

__global__ __launch_bounds__(256) void gemm_hmma_kernel(
    const float* __restrict__ bias, float* __restrict__ C)
{
    __shared__ __align__(16) __half As[2][64 * HAPITCH];
    __shared__ __align__(16) __half Bs[2][32 * HBPITCH];

    const int tid  = threadIdx.x;
    const int wid  = tid >> 5;
    const int lane = tid & 31;
    const int m0 = blockIdx.y * 64;
    const int n0 = blockIdx.x * 128;
    const int wm = (wid & 1) * 32;       // 2 m-warps
    const int wn = (wid >> 1) * 32;      // 4 n-warps

    const int ara = tid >> 2;            // A row 0..63, 1 cp16/thread
    const int aca = (tid & 3) * 8;
    const int brb = tid >> 4;            // B k-row 0..15 (+16)
    const int bcb = (tid & 15) * 8;

    float acc[2][4][4] = {};

    const int lr = lane & 15;
    const int lc = (lane >> 4) * 8;

    {
        const int k0 = 0;
        cpa16(smem_u32(&As[0][ara * HAPITCH + aca]),
              &g_pre16[(size_t)(m0 + ara) * 256 + k0 + aca]);
        cpa16(smem_u32(&Bs[0][brb * HBPITCH + bcb]),
              &g_Wout16[(size_t)(k0 + brb) * 256 + n0 + bcb]);
        cpa16(smem_u32(&Bs[0][(brb + 16) * HBPITCH + bcb]),
              &g_Wout16[(size_t)(k0 + brb + 16) * 256 + n0 + bcb]);
        asm volatile("cp.async.commit_group;");
    }

#pragma unroll
    for (int it = 0; it < 8; it++) {
        if (it + 1 < 8) {
            const int k0 = (it + 1) * 32;
            const int s = (it + 1) & 1;
            cpa16(smem_u32(&As[s][ara * HAPITCH + aca]),
                  &g_pre16[(size_t)(m0 + ara) * 256 + k0 + aca]);
            cpa16(smem_u32(&Bs[s][brb * HBPITCH + bcb]),
                  &g_Wout16[(size_t)(k0 + brb) * 256 + n0 + bcb]);
            cpa16(smem_u32(&Bs[s][(brb + 16) * HBPITCH + bcb]),
                  &g_Wout16[(size_t)(k0 + brb + 16) * 256 + n0 + bcb]);
            asm volatile("cp.async.commit_group;");
            asm volatile("cp.async.wait_group 1;");
        } else {
            asm volatile("cp.async.wait_group 0;");
        }
        __syncthreads();

        const int s = it & 1;
#pragma unroll
        for (int kk = 0; kk < 32; kk += 16) {
            unsigned a[2][4];
#pragma unroll
            for (int mt = 0; mt < 2; mt++) {
                unsigned addr = smem_u32(&As[s][(wm + mt * 16 + lr) * HAPITCH + kk + lc]);
                asm volatile(
                    "ldmatrix.sync.aligned.m8n8.x4.shared.b16 {%0,%1,%2,%3}, [%4];"
                    : "=r"(a[mt][0]), "=r"(a[mt][1]), "=r"(a[mt][2]), "=r"(a[mt][3])
                    : "r"(addr));
            }
            unsigned b[2][4];
#pragma unroll
            for (int ng = 0; ng < 2; ng++) {
                unsigned addr = smem_u32(&Bs[s][(kk + lr) * HBPITCH + wn + ng * 16 + lc]);
                asm volatile(
                    "ldmatrix.sync.aligned.m8n8.x4.trans.shared.b16 {%0,%1,%2,%3}, [%4];"
                    : "=r"(b[ng][0]), "=r"(b[ng][1]), "=r"(b[ng][2]), "=r"(b[ng][3])
                    : "r"(addr));
            }
#pragma unroll
            for (int mt = 0; mt < 2; mt++) {
#pragma unroll
                for (int nt = 0; nt < 4; nt++) {
                    unsigned b0 = b[nt >> 1][(nt & 1) * 2 + 0];
                    unsigned b1 = b[nt >> 1][(nt & 1) * 2 + 1];
                    asm volatile(
                        "mma.sync.aligned.m16n8k16.row.col.f32.f16.f16.f32 "
                        "{%0,%1,%2,%3}, {%4,%5,%6,%7}, {%8,%9}, {%0,%1,%2,%3};"
                        : "+f"(acc[mt][nt][0]), "+f"(acc[mt][nt][1]),
                          "+f"(acc[mt][nt][2]), "+f"(acc[mt][nt][3])
                        : "r"(a[mt][0]), "r"(a[mt][1]), "r"(a[mt][2]), "r"(a[mt][3]),
                          "r"(b0), "r"(b1));
                }
            }
        }
        __syncthreads();
    }

    const int gr = lane >> 2;
    const int gc = (lane & 3) * 2;
#pragma unroll
    for (int mt = 0; mt < 2; mt++) {
#pragma unroll
        for (int nt = 0; nt < 4; nt++) {
            int col = n0 + wn + nt * 8 + gc;
            float2 bv = *(const float2*)&bias[col];
            int row0 = m0 + wm + mt * 16 + gr;
            float2 o0 = make_float2(acc[mt][nt][0] + bv.x, acc[mt][nt][1] + bv.y);
            float2 o1 = make_float2(acc[mt][nt][2] + bv.x, acc[mt][nt][3] + bv.y);
            *(float2*)&C[(size_t)row0 * 256 + col]       = o0;
            *(float2*)&C[(size_t)(row0 + 8) * 256 + col] = o1;
        }
    }
}

// ---------------------------------------------------------------------------
extern "C" void kernel_launch(void* const* d_in, const int* in_sizes, int n_in,
                              void* d_out, int out_size)
{
    const float* q        = (const float*)d_in[0];
    const float* map0     = (const float*)d_in[1];
    const float* map1     = (const float*)d_in[2];
    const float* base_ref = (const float*)d_in[3];
    const float* Wrd      = (const float*)d_in[4];
    const float* brd      = (const float*)d_in[5];
    const float* Woff     = (const float*)d_in[6];
    const float* boff     = (const float*)d_in[7];
    const float* Wattn    = (const float*)d_in[8];
    const float* battn    = (const float*)d_in[9];
    const float* Wout     = (const float*)d_in[10];
    const float* bout     = (const float*)d_in[11];
    float* out = (float*)d_out;

    pack_all_kernel<<<192, 256>>>(Wrd, brd, Woff, boff, Wattn, battn, Wout);

    transpose_both_kernel<<<dim3(512 + 128, Dm / 64, Bn), 256>>>(map0, map1);

    proj_hmma_kernel<<<NQ / 64, 256>>>(q);

    gather_fused_kernel<<<NQ / 16, 256>>>(base_ref);

    gemm_hmma_kernel<<<dim3(2, NQ / 64), 256>>>(bout, out);
}